// round 9
// baseline (speedup 1.0000x reference)
#include <cuda_runtime.h>
#include <math.h>

#define BATCH  16
#define CC     64
#define MM     4096
#define NSPLIT 32     // 128-col chunk per block -> 512 blocks
#define CHUNK  128
#define NKB    (CHUNK / 64)
#define LDS    68     // smem row stride (words); 68 % 32 == 4 -> conflict-free frags
#define LDP    68     // ns smem row stride (same property)

// Deterministic scratch (no float atomics)
__device__ float g_part[BATCH * NSPLIT * CC * CC];   // 8 MB partial Grams (L2-resident)
__device__ float g_rspart[BATCH * NSPLIT * CC];
__device__ float g_scale[BATCH * CC];

__device__ __forceinline__ unsigned cvt_tf32(float f) {
    unsigned r; asm("cvt.rna.tf32.f32 %0, %1;" : "=r"(r) : "f"(f)); return r;
}
__device__ __forceinline__ float tf32f(float f) {          // round to tf32, keep as float
    return __uint_as_float(cvt_tf32(f));
}
__device__ __forceinline__ void mma_tf32(float c[4], unsigned a0, unsigned a1,
                                         unsigned a2, unsigned a3,
                                         unsigned b0, unsigned b1) {
    asm("mma.sync.aligned.m16n8k8.row.col.f32.tf32.tf32.f32 "
        "{%0,%1,%2,%3},{%4,%5,%6,%7},{%8,%9},{%0,%1,%2,%3};"
        : "+f"(c[0]), "+f"(c[1]), "+f"(c[2]), "+f"(c[3])
        : "r"(a0), "r"(a1), "r"(a2), "r"(a3), "r"(b0), "r"(b1));
}

// ---------------------------------------------------------------------------
// Kernel 1: partial X·X^T per (batch, 128-col chunk) via tf32 mma.sync,
// + fp32 partial row sums. grid (NSPLIT, BATCH) = 512 blocks, 256 threads.
// Software pipeline: tile kb+1 LDGs are issued before the mma loop on tile kb,
// so the load latency hides under tensor work.
// ---------------------------------------------------------------------------
__global__ __launch_bounds__(256) void cov_kernel(const float* __restrict__ x) {
    __shared__ unsigned buf[64 * LDS];
    const int split = blockIdx.x, b = blockIdx.y;
    const int t = threadIdx.x;
    const int lane = t & 31, w = t >> 5;
    const int m0 = 16 * (w & 3);
    const int n0base = 32 * (w >> 2);
    const int g = lane >> 2, tg = lane & 3;
    const int lrow = t >> 4, lcg = t & 15;
    const float* xb = x + (size_t)b * CC * MM + (size_t)split * CHUNK;

    float c[4][4];
#pragma unroll
    for (int j = 0; j < 4; j++)
#pragma unroll
        for (int q = 0; q < 4; q++) c[j][q] = 0.f;
    float rs[4] = {0.f, 0.f, 0.f, 0.f};

    float4 v[4];
    // Prologue: load tile 0 into registers.
#pragma unroll
    for (int j = 0; j < 4; j++)
        v[j] = *(const float4*)&xb[(size_t)(j * 16 + lrow) * MM + 4 * lcg];

    for (int kb = 0; kb < NKB; kb++) {
        __syncthreads();   // previous mma done reading buf
        // Store current tile (tf32 bits) + accumulate fp32 row sums.
#pragma unroll
        for (int j = 0; j < 4; j++) {
            int row = j * 16 + lrow;
            rs[j] += (v[j].x + v[j].y) + (v[j].z + v[j].w);
            uint4 u;
            u.x = cvt_tf32(v[j].x); u.y = cvt_tf32(v[j].y);
            u.z = cvt_tf32(v[j].z); u.w = cvt_tf32(v[j].w);
            *(uint4*)&buf[row * LDS + 4 * lcg] = u;
        }
        __syncthreads();
        // Prefetch next tile: LDGs in flight during the mma loop below.
        if (kb + 1 < NKB) {
#pragma unroll
            for (int j = 0; j < 4; j++)
                v[j] = *(const float4*)&xb[(size_t)(j * 16 + lrow) * MM + (kb + 1) * 64 + 4 * lcg];
        }
        // 8 k-steps of m16n8k8; all frag loads conflict-free (LDS%32==4).
#pragma unroll
        for (int k0 = 0; k0 < 64; k0 += 8) {
            unsigned a0 = buf[(m0 + g) * LDS + k0 + tg];
            unsigned a1 = buf[(m0 + g + 8) * LDS + k0 + tg];
            unsigned a2 = buf[(m0 + g) * LDS + k0 + tg + 4];
            unsigned a3 = buf[(m0 + g + 8) * LDS + k0 + tg + 4];
#pragma unroll
            for (int j = 0; j < 4; j++) {
                int n0 = n0base + 8 * j;
                unsigned b0 = buf[(n0 + g) * LDS + k0 + tg];
                unsigned b1 = buf[(n0 + g) * LDS + k0 + tg + 4];
                mma_tf32(c[j], a0, a1, a2, a3, b0, b1);
            }
        }
    }

    // Epilogue: write partial Gram fragments.
    float* P = g_part + (((size_t)(b * NSPLIT + split)) << 12);
#pragma unroll
    for (int j = 0; j < 4; j++) {
        int row = m0 + g, col = n0base + 8 * j + 2 * tg;
        *(float2*)&P[row * 64 + col]       = make_float2(c[j][0], c[j][1]);
        *(float2*)&P[(row + 8) * 64 + col] = make_float2(c[j][2], c[j][3]);
    }

    // Row sums: reduce 16 per-colgroup partials per row via smem scratch.
    __syncthreads();
    float* rsm = (float*)buf;
#pragma unroll
    for (int j = 0; j < 4; j++)
        rsm[(j * 16 + lrow) * 17 + lcg] = rs[j];
    __syncthreads();
    if (t < 64) {
        float s = 0.f;
#pragma unroll
        for (int i = 0; i < 16; i++) s += rsm[t * 17 + i];
        g_rspart[(b * NSPLIT + split) * 64 + t] = s;
    }
}

// ---------------------------------------------------------------------------
// 64x64x64 matmul via tf32 mma.sync. Matrices stored pre-rounded to tf32 bit
// patterns, so operand loads need no cvt. NS is self-correcting; SE tail
// attenuates ~100x. C = A@B (mode 0) or C = 0.5*(3I - A@B) (mode 1).
// VALID ONLY FOR SYMMETRIC B (all NS matrices are polynomials of symmetric A).
// 256 threads = 8 warps; warp w: rows 16*(w&3)+, cols 32*(w>>2)+.
// ---------------------------------------------------------------------------
__device__ __forceinline__ void mm64t(float* __restrict__ C, const float* __restrict__ A,
                                      const float* __restrict__ B, int w, int lane, int mode) {
    const int m0 = 16 * (w & 3);
    const int n0b = 32 * (w >> 2);
    const int g = lane >> 2, tg = lane & 3;
    const unsigned* Au = (const unsigned*)A;
    const unsigned* Bu = (const unsigned*)B;

    float c[4][4];
#pragma unroll
    for (int j = 0; j < 4; j++)
#pragma unroll
        for (int q = 0; q < 4; q++) c[j][q] = 0.f;

#pragma unroll
    for (int k0 = 0; k0 < 64; k0 += 8) {
        unsigned a0 = Au[(m0 + g) * LDP + k0 + tg];
        unsigned a1 = Au[(m0 + g + 8) * LDP + k0 + tg];
        unsigned a2 = Au[(m0 + g) * LDP + k0 + tg + 4];
        unsigned a3 = Au[(m0 + g + 8) * LDP + k0 + tg + 4];
#pragma unroll
        for (int j = 0; j < 4; j++) {
            int n0 = n0b + 8 * j;
            unsigned b0 = Bu[(n0 + g) * LDP + k0 + tg];
            unsigned b1 = Bu[(n0 + g) * LDP + k0 + tg + 4];
            mma_tf32(c[j], a0, a1, a2, a3, b0, b1);
        }
    }
    __syncthreads();   // all operand reads done before C overwrites anything
#pragma unroll
    for (int j = 0; j < 4; j++) {
        int col = n0b + 8 * j + 2 * tg;
        int r0 = m0 + g, r1 = m0 + g + 8;
        float v0 = c[j][0], v1 = c[j][1], v2 = c[j][2], v3 = c[j][3];
        if (mode) {
            v0 = 0.5f * (((r0 == col)     ? 3.f : 0.f) - v0);
            v1 = 0.5f * (((r0 == col + 1) ? 3.f : 0.f) - v1);
            v2 = 0.5f * (((r1 == col)     ? 3.f : 0.f) - v2);
            v3 = 0.5f * (((r1 == col + 1) ? 3.f : 0.f) - v3);
        }
        *(float2*)&C[r0 * LDP + col] = make_float2(tf32f(v0), tf32f(v1));
        *(float2*)&C[r1 * LDP + col] = make_float2(tf32f(v2), tf32f(v3));
    }
    __syncthreads();   // C visible
}

// ---------------------------------------------------------------------------
// Kernel 2: partial-Gram reduction + covariance assembly + Newton-Schulz
// (tensor) + center-tap convs. 16 blocks x 256 threads.
// The split reduction happens inline (32-way MLP L2 reads) — no extra kernel.
// ---------------------------------------------------------------------------
__global__ __launch_bounds__(256) void ns_kernel(const float* __restrict__ w1, const float* __restrict__ b1,
                                                 const float* __restrict__ w2, const float* __restrict__ b2) {
    extern __shared__ float sm[];
    float* S0 = sm;
    float* S1 = sm + 64 * LDP;
    float* S2 = sm + 2 * 64 * LDP;
    float* S3 = sm + 3 * 64 * LDP;
    __shared__ float svec[64];
    __shared__ float vvec[64];
    __shared__ float red[8];
    __shared__ float snorm;

    const int b = blockIdx.x, t = threadIdx.x;
    const int lane = t & 31, w = t >> 5;
    const float invM = 1.0f / (float)MM;
    const float invM2 = invM * invM;

    // row sums (reduce split partials)
    if (t < 64) {
        float s = 0.f;
#pragma unroll
        for (int sp = 0; sp < NSPLIT; sp++) s += g_rspart[(b * NSPLIT + sp) * 64 + t];
        svec[t] = s;
    }
    __syncthreads();

    // cov = Sxx/M - s s^T / M^2 ; normA = sum(cov). Sxx summed from g_part
    // inline: inner loop is 32 independent L2 loads (high MLP).
    const float* Pb = g_part + ((size_t)b * NSPLIT << 12);
    float lsum = 0.f;
#pragma unroll
    for (int e = 0; e < 16; e++) {
        int idx = e * 256 + t;
        int i = idx >> 6, j = idx & 63;
        float s = 0.f;
#pragma unroll
        for (int sp = 0; sp < NSPLIT; sp++)
            s += Pb[((size_t)sp << 12) + idx];
        float cv = invM * s - invM2 * svec[i] * svec[j];
        S0[i * LDP + j] = cv;
        lsum += cv;
    }
#pragma unroll
    for (int o = 16; o; o >>= 1) lsum += __shfl_xor_sync(0xffffffffu, lsum, o);
    if ((t & 31) == 0) red[t >> 5] = lsum;
    __syncthreads();
    if (t == 0) { float s = 0.f; for (int q = 0; q < 8; q++) s += red[q]; snorm = s; }
    __syncthreads();

    const float invN = 1.f / snorm;
#pragma unroll
    for (int e = 0; e < 16; e++) {
        int idx = e * 256 + t;
        int i = idx >> 6, j = idx & 63;
        float a = S0[i * LDP + j] * invN;
        S0[i * LDP + j] = tf32f(a);
        float zy = 0.5f * (((i == j) ? 3.f : 0.f) - a);
        float zyt = tf32f(zy);
        S3[i * LDP + j] = zyt;   // ZY
        S2[i * LDP + j] = zyt;   // Z = ZY
    }
    __syncthreads();

    mm64t(S1, S0, S3, w, lane, 0);   // Y = A @ ZY

    float* pY = S1; float* pZ = S2; float* pT = S0; float* pU = S3;
    for (int it = 0; it < 3; it++) {
        mm64t(pT, pZ, pY, w, lane, 1);   // T = 0.5(3I - Z@Y) = ZYnew
        mm64t(pU, pY, pT, w, lane, 0);   // U = Ynew = Y @ ZYnew
        mm64t(pY, pT, pZ, w, lane, 0);   // (old Y slot) = Znew = ZYnew @ Z
        float* oY = pY; float* oZ = pZ; float* oT = pT; float* oU = pU;
        pY = oU; pZ = oY; pT = oT; pU = oZ;
    }

    // Stage conv center taps into the two dead smem matrices (parallel loads).
    float* W1 = pT;
    float* W2 = pU;
#pragma unroll
    for (int e = 0; e < 16; e++) {
        int n = e * 256 + t;                 // n = outc*64 + inc
        W1[n] = w1[n * 9 + 4];
        W2[n] = w2[n * 9 + 4];
    }

    // y_vec = (0.5/64)*sqrt(normA) * (3u - (u^T Z) Y), u = colsum(Y)
    __syncthreads();
    if (t < 64) {
        float u = 0.f;
        for (int i = 0; i < 64; i++) u += pY[i * LDP + t];
        svec[t] = u;
    }
    __syncthreads();
    if (t < 64) {
        float vv = 0.f;
        for (int i = 0; i < 64; i++) vv += svec[i] * pZ[i * LDP + t];
        vvec[t] = vv;
    }
    __syncthreads();
    if (t < 64) {
        float wv = 0.f;
        for (int k = 0; k < 64; k++) wv += vvec[k] * pY[k * LDP + t];
        float c = (0.5f / 64.f) * sqrtf(snorm);
        svec[t] = c * (3.f * svec[t] - wv);   // y_vec
    }
    __syncthreads();
    // conv1 center tap + bias + relu
    if (t < 64) {
        float a = b1[t];
        for (int i = 0; i < 64; i++) a += W1[t * 64 + i] * svec[i];
        vvec[t] = fmaxf(a, 0.f);
    }
    __syncthreads();
    // conv2 center tap + bias + sigmoid
    if (t < 64) {
        float a = b2[t];
        for (int i = 0; i < 64; i++) a += W2[t * 64 + i] * vvec[i];
        g_scale[b * 64 + t] = 1.f / (1.f + expf(-a));
    }
}

// ---------------------------------------------------------------------------
// Kernel 3: out = scale[b,c] * x via pipelined cp.async.bulk.
// 256 blocks x 2 chunks of 32KB (both loads issued up-front; wait/mult/store).
// ---------------------------------------------------------------------------
#define SC_CHF 8192                 // floats per chunk (32KB)
#define SC_NCH 2                    // chunks per block
__global__ __launch_bounds__(256) void scale_kernel(const float* __restrict__ x,
                                                    float* __restrict__ out) {
    extern __shared__ __align__(16) float sbuf[];        // SC_NCH * 8192 floats
    __shared__ __align__(8) unsigned long long mbar[SC_NCH];
    const int t = threadIdx.x;
    const size_t blockbase = (size_t)blockIdx.x * (SC_NCH * SC_CHF);

    unsigned sb = (unsigned)__cvta_generic_to_shared(sbuf);
    unsigned mb = (unsigned)__cvta_generic_to_shared(mbar);

    if (t == 0) {
#pragma unroll
        for (int c = 0; c < SC_NCH; c++)
            asm volatile("mbarrier.init.shared.b64 [%0], 1;" :: "r"(mb + 8 * c) : "memory");
    }
    __syncthreads();
    if (t == 0) {
#pragma unroll
        for (int c = 0; c < SC_NCH; c++) {
            asm volatile("mbarrier.arrive.expect_tx.shared.b64 _, [%0], %1;"
                         :: "r"(mb + 8 * c), "r"(32768u) : "memory");
            asm volatile("cp.async.bulk.shared::cta.global.mbarrier::complete_tx::bytes "
                         "[%0], [%1], %2, [%3];"
                         :: "r"(sb + c * 32768u), "l"(x + blockbase + (size_t)c * SC_CHF),
                            "r"(32768u), "r"(mb + 8 * c) : "memory");
        }
    }

#pragma unroll
    for (int c = 0; c < SC_NCH; c++) {
        // Wait for this chunk's bulk load (phase 0; each barrier used once).
        asm volatile(
            "{\n\t.reg .pred p;\n"
            "WL%=:\n\t"
            "mbarrier.try_wait.parity.shared.b64 p, [%0], 0, 0x989680;\n\t"
            "@!p bra WL%=;\n\t}"
            :: "r"(mb + 8 * c) : "memory");

        // Multiply in place: 8 float4/thread. chunk covers 2 channels (4096 fl each).
        float4* s4 = (float4*)(sbuf + c * SC_CHF);
        const size_t cbase = blockbase + (size_t)c * SC_CHF;
        const int ch0 = (int)(cbase >> 12);
        float sc0 = g_scale[ch0], sc1 = g_scale[ch0 + 1];
#pragma unroll
        for (int j = 0; j < 8; j++) {
            int li = j * 256 + t;                        // float4 index in chunk
            float s = (li < 1024) ? sc0 : sc1;
            float4 vv = s4[li];
            vv.x *= s; vv.y *= s; vv.z *= s; vv.w *= s;
            s4[li] = vv;
        }
        __syncthreads();
        asm volatile("fence.proxy.async.shared::cta;" ::: "memory");
        if (t == 0) {
            asm volatile("cp.async.bulk.global.shared::cta.bulk_group [%0], [%1], %2;"
                         :: "l"(out + cbase), "r"(sb + c * 32768u), "r"(32768u) : "memory");
            asm volatile("cp.async.bulk.commit_group;" ::: "memory");
        }
    }
    if (t == 0)
        asm volatile("cp.async.bulk.wait_group.read 0;" ::: "memory");
}

extern "C" void kernel_launch(void* const* d_in, const int* in_sizes, int n_in,
                              void* d_out, int out_size) {
    const float* x  = (const float*)d_in[0];
    const float* w1 = (const float*)d_in[1];
    const float* b1 = (const float*)d_in[2];
    const float* w2 = (const float*)d_in[3];
    const float* b2 = (const float*)d_in[4];
    float* out = (float*)d_out;

    (void)in_sizes; (void)n_in; (void)out_size;

    const int ns_smem = 4 * 64 * LDP * (int)sizeof(float);
    cudaFuncSetAttribute(ns_kernel, cudaFuncAttributeMaxDynamicSharedMemorySize, ns_smem);
    const int sc_smem = SC_NCH * SC_CHF * (int)sizeof(float);   // 64 KB
    cudaFuncSetAttribute(scale_kernel, cudaFuncAttributeMaxDynamicSharedMemorySize, sc_smem);

    dim3 gcov(NSPLIT, BATCH);
    cov_kernel<<<gcov, 256>>>(x);
    ns_kernel<<<BATCH, 256, ns_smem>>>(w1, b1, w2, b2);
    scale_kernel<<<(BATCH * CC * MM) / (SC_NCH * SC_CHF), 256, sc_smem>>>(x, out);
}

// round 10
// speedup vs baseline: 1.3514x; 1.3514x over previous
#include <cuda_runtime.h>
#include <math.h>

#define BATCH  16
#define CC     64
#define MM     4096
#define NSPLIT 64     // one 64-col tile per block -> 1024 blocks
#define LDS    68     // smem row stride (words); 68 % 32 == 4 -> conflict-free frags
#define LDP    68     // ns smem row stride (same property)

// Deterministic scratch (no float atomics)
__device__ float g_part[BATCH * NSPLIT * CC * CC];   // 16.8 MB partial Grams (L2-resident)
__device__ float g_rspart[BATCH * NSPLIT * CC];
__device__ float g_cov[BATCH * CC * CC];
__device__ float g_scale[BATCH * CC];

__device__ __forceinline__ unsigned cvt_tf32(float f) {
    unsigned r; asm("cvt.rna.tf32.f32 %0, %1;" : "=r"(r) : "f"(f)); return r;
}
__device__ __forceinline__ float tf32f(float f) {          // round to tf32, keep as float
    return __uint_as_float(cvt_tf32(f));
}
__device__ __forceinline__ void mma_tf32(float c[4], unsigned a0, unsigned a1,
                                         unsigned a2, unsigned a3,
                                         unsigned b0, unsigned b1) {
    asm("mma.sync.aligned.m16n8k8.row.col.f32.tf32.tf32.f32 "
        "{%0,%1,%2,%3},{%4,%5,%6,%7},{%8,%9},{%0,%1,%2,%3};"
        : "+f"(c[0]), "+f"(c[1]), "+f"(c[2]), "+f"(c[3])
        : "r"(a0), "r"(a1), "r"(a2), "r"(a3), "r"(b0), "r"(b1));
}

// ---------------------------------------------------------------------------
// Kernel 1: partial X·X^T per (batch, 64-col tile) via tf32 mma.sync,
// + fp32 partial row sums. grid (NSPLIT, BATCH) = 1024 blocks (~7 CTAs/SM),
// 256 threads. Single tile per block: no k-loop, no inter-tile syncs; DRAM
// latency is hidden by cross-CTA overlap.
// Warp w: rows [16*(w&3), +16), cols [32*(w>>2), +32).
// ---------------------------------------------------------------------------
__global__ __launch_bounds__(256) void cov_kernel(const float* __restrict__ x) {
    __shared__ unsigned buf[64 * LDS];
    const int split = blockIdx.x, b = blockIdx.y;
    const int t = threadIdx.x;
    const int lane = t & 31, w = t >> 5;
    const int m0 = 16 * (w & 3);
    const int n0base = 32 * (w >> 2);
    const int g = lane >> 2, tg = lane & 3;
    const int lrow = t >> 4, lcg = t & 15;
    const float* xb = x + (size_t)b * CC * MM + (size_t)split * 64;

    // Front-batched loads (MLP=4 float4 = 8 lines in flight per thread).
    float4 v[4];
#pragma unroll
    for (int j = 0; j < 4; j++)
        v[j] = *(const float4*)&xb[(size_t)(j * 16 + lrow) * MM + 4 * lcg];

    float rs[4];
#pragma unroll
    for (int j = 0; j < 4; j++) {
        int row = j * 16 + lrow;
        rs[j] = (v[j].x + v[j].y) + (v[j].z + v[j].w);
        uint4 u;
        u.x = cvt_tf32(v[j].x); u.y = cvt_tf32(v[j].y);
        u.z = cvt_tf32(v[j].z); u.w = cvt_tf32(v[j].w);
        *(uint4*)&buf[row * LDS + 4 * lcg] = u;
    }
    __syncthreads();

    float c[4][4];
#pragma unroll
    for (int j = 0; j < 4; j++)
#pragma unroll
        for (int q = 0; q < 4; q++) c[j][q] = 0.f;

    // 8 k-steps of m16n8k8; all frag loads conflict-free (LDS%32==4).
#pragma unroll
    for (int k0 = 0; k0 < 64; k0 += 8) {
        unsigned a0 = buf[(m0 + g) * LDS + k0 + tg];
        unsigned a1 = buf[(m0 + g + 8) * LDS + k0 + tg];
        unsigned a2 = buf[(m0 + g) * LDS + k0 + tg + 4];
        unsigned a3 = buf[(m0 + g + 8) * LDS + k0 + tg + 4];
#pragma unroll
        for (int j = 0; j < 4; j++) {
            int n0 = n0base + 8 * j;
            unsigned b0 = buf[(n0 + g) * LDS + k0 + tg];
            unsigned b1 = buf[(n0 + g) * LDS + k0 + tg + 4];
            mma_tf32(c[j], a0, a1, a2, a3, b0, b1);
        }
    }

    // Epilogue: write partial Gram fragments.
    float* P = g_part + (((size_t)(b * NSPLIT + split)) << 12);
#pragma unroll
    for (int j = 0; j < 4; j++) {
        int row = m0 + g, col = n0base + 8 * j + 2 * tg;
        *(float2*)&P[row * 64 + col]       = make_float2(c[j][0], c[j][1]);
        *(float2*)&P[(row + 8) * 64 + col] = make_float2(c[j][2], c[j][3]);
    }

    // Row sums: reduce 16 per-colgroup partials per row via smem scratch.
    __syncthreads();
    float* rsm = (float*)buf;
#pragma unroll
    for (int j = 0; j < 4; j++)
        rsm[(j * 16 + lrow) * 17 + lcg] = rs[j];
    __syncthreads();
    if (t < 64) {
        float s = 0.f;
#pragma unroll
        for (int i = 0; i < 16; i++) s += rsm[t * 17 + i];
        g_rspart[(b * NSPLIT + split) * 64 + t] = s;
    }
}

// ---------------------------------------------------------------------------
// Kernel 2: reduce partial Grams across splits (fully parallel, L2-bound).
// 256 blocks; per-thread 64-way MLP inner loop.
// ---------------------------------------------------------------------------
__global__ __launch_bounds__(256) void reduce_kernel() {
    int idx = blockIdx.x * 256 + threadIdx.x;       // 0 .. 16*4096-1
    int b = idx >> 12, e = idx & 4095;
    float s = 0.f;
#pragma unroll
    for (int sp = 0; sp < NSPLIT; sp++)
        s += g_part[(((size_t)(b * NSPLIT + sp)) << 12) + e];
    g_cov[idx] = s;
}

// ---------------------------------------------------------------------------
// 64x64x64 matmul via tf32 mma.sync. Matrices stored pre-rounded to tf32 bit
// patterns, so operand loads need no cvt. NS is self-correcting; SE tail
// attenuates ~100x. C = A@B (mode 0) or C = 0.5*(3I - A@B) (mode 1).
// VALID ONLY FOR SYMMETRIC B (all NS matrices are polynomials of symmetric A).
// 256 threads = 8 warps; warp w: rows 16*(w&3)+, cols 32*(w>>2)+.
// ---------------------------------------------------------------------------
__device__ __forceinline__ void mm64t(float* __restrict__ C, const float* __restrict__ A,
                                      const float* __restrict__ B, int w, int lane, int mode) {
    const int m0 = 16 * (w & 3);
    const int n0b = 32 * (w >> 2);
    const int g = lane >> 2, tg = lane & 3;
    const unsigned* Au = (const unsigned*)A;
    const unsigned* Bu = (const unsigned*)B;

    float c[4][4];
#pragma unroll
    for (int j = 0; j < 4; j++)
#pragma unroll
        for (int q = 0; q < 4; q++) c[j][q] = 0.f;

#pragma unroll
    for (int k0 = 0; k0 < 64; k0 += 8) {
        unsigned a0 = Au[(m0 + g) * LDP + k0 + tg];
        unsigned a1 = Au[(m0 + g + 8) * LDP + k0 + tg];
        unsigned a2 = Au[(m0 + g) * LDP + k0 + tg + 4];
        unsigned a3 = Au[(m0 + g + 8) * LDP + k0 + tg + 4];
#pragma unroll
        for (int j = 0; j < 4; j++) {
            int n0 = n0b + 8 * j;
            unsigned b0 = Bu[(n0 + g) * LDP + k0 + tg];
            unsigned b1 = Bu[(n0 + g) * LDP + k0 + tg + 4];
            mma_tf32(c[j], a0, a1, a2, a3, b0, b1);
        }
    }
    __syncthreads();   // all operand reads done before C overwrites anything
#pragma unroll
    for (int j = 0; j < 4; j++) {
        int col = n0b + 8 * j + 2 * tg;
        int r0 = m0 + g, r1 = m0 + g + 8;
        float v0 = c[j][0], v1 = c[j][1], v2 = c[j][2], v3 = c[j][3];
        if (mode) {
            v0 = 0.5f * (((r0 == col)     ? 3.f : 0.f) - v0);
            v1 = 0.5f * (((r0 == col + 1) ? 3.f : 0.f) - v1);
            v2 = 0.5f * (((r1 == col)     ? 3.f : 0.f) - v2);
            v3 = 0.5f * (((r1 == col + 1) ? 3.f : 0.f) - v3);
        }
        *(float2*)&C[r0 * LDP + col] = make_float2(tf32f(v0), tf32f(v1));
        *(float2*)&C[r1 * LDP + col] = make_float2(tf32f(v2), tf32f(v3));
    }
    __syncthreads();   // C visible
}

// ---------------------------------------------------------------------------
// Kernel 3: covariance assembly + Newton-Schulz (tensor) + center-tap convs.
// 16 blocks x 256 threads. Dynamic smem: 4 matrices [64][LDP].
// ---------------------------------------------------------------------------
__global__ __launch_bounds__(256) void ns_kernel(const float* __restrict__ w1, const float* __restrict__ b1,
                                                 const float* __restrict__ w2, const float* __restrict__ b2) {
    extern __shared__ float sm[];
    float* S0 = sm;
    float* S1 = sm + 64 * LDP;
    float* S2 = sm + 2 * 64 * LDP;
    float* S3 = sm + 3 * 64 * LDP;
    __shared__ float svec[64];
    __shared__ float vvec[64];
    __shared__ float red[8];
    __shared__ float snorm;

    const int b = blockIdx.x, t = threadIdx.x;
    const int lane = t & 31, w = t >> 5;
    const float invM = 1.0f / (float)MM;
    const float invM2 = invM * invM;

    // row sums (reduce split partials)
    if (t < 64) {
        float s = 0.f;
#pragma unroll
        for (int sp = 0; sp < NSPLIT; sp++) s += g_rspart[(b * NSPLIT + sp) * 64 + t];
        svec[t] = s;
    }
    __syncthreads();

    // cov = Sxx/M - s s^T / M^2 ; normA = sum(cov)  (fp32-exact for snorm)
    float lsum = 0.f;
#pragma unroll
    for (int e = 0; e < 16; e++) {
        int idx = e * 256 + t;
        int i = idx >> 6, j = idx & 63;
        float cv = invM * g_cov[b * 4096 + idx] - invM2 * svec[i] * svec[j];
        S0[i * LDP + j] = cv;
        lsum += cv;
    }
#pragma unroll
    for (int o = 16; o; o >>= 1) lsum += __shfl_xor_sync(0xffffffffu, lsum, o);
    if ((t & 31) == 0) red[t >> 5] = lsum;
    __syncthreads();
    if (t == 0) { float s = 0.f; for (int q = 0; q < 8; q++) s += red[q]; snorm = s; }
    __syncthreads();

    const float invN = 1.f / snorm;
#pragma unroll
    for (int e = 0; e < 16; e++) {
        int idx = e * 256 + t;
        int i = idx >> 6, j = idx & 63;
        float a = S0[i * LDP + j] * invN;
        S0[i * LDP + j] = tf32f(a);
        float zy = 0.5f * (((i == j) ? 3.f : 0.f) - a);
        float zyt = tf32f(zy);
        S3[i * LDP + j] = zyt;   // ZY
        S2[i * LDP + j] = zyt;   // Z = ZY
    }
    __syncthreads();

    mm64t(S1, S0, S3, w, lane, 0);   // Y = A @ ZY

    float* pY = S1; float* pZ = S2; float* pT = S0; float* pU = S3;
    for (int it = 0; it < 3; it++) {
        mm64t(pT, pZ, pY, w, lane, 1);   // T = 0.5(3I - Z@Y) = ZYnew
        mm64t(pU, pY, pT, w, lane, 0);   // U = Ynew = Y @ ZYnew
        mm64t(pY, pT, pZ, w, lane, 0);   // (old Y slot) = Znew = ZYnew @ Z
        float* oY = pY; float* oZ = pZ; float* oT = pT; float* oU = pU;
        pY = oU; pZ = oY; pT = oT; pU = oZ;
    }

    // Stage conv center taps into the two dead smem matrices (parallel loads).
    float* W1 = pT;
    float* W2 = pU;
#pragma unroll
    for (int e = 0; e < 16; e++) {
        int n = e * 256 + t;                 // n = outc*64 + inc
        W1[n] = w1[n * 9 + 4];
        W2[n] = w2[n * 9 + 4];
    }

    // y_vec = (0.5/64)*sqrt(normA) * (3u - (u^T Z) Y), u = colsum(Y)
    __syncthreads();
    if (t < 64) {
        float u = 0.f;
        for (int i = 0; i < 64; i++) u += pY[i * LDP + t];
        svec[t] = u;
    }
    __syncthreads();
    if (t < 64) {
        float vv = 0.f;
        for (int i = 0; i < 64; i++) vv += svec[i] * pZ[i * LDP + t];
        vvec[t] = vv;
    }
    __syncthreads();
    if (t < 64) {
        float wv = 0.f;
        for (int k = 0; k < 64; k++) wv += vvec[k] * pY[k * LDP + t];
        float c = (0.5f / 64.f) * sqrtf(snorm);
        svec[t] = c * (3.f * svec[t] - wv);   // y_vec
    }
    __syncthreads();
    // conv1 center tap + bias + relu
    if (t < 64) {
        float a = b1[t];
        for (int i = 0; i < 64; i++) a += W1[t * 64 + i] * svec[i];
        vvec[t] = fmaxf(a, 0.f);
    }
    __syncthreads();
    // conv2 center tap + bias + sigmoid
    if (t < 64) {
        float a = b2[t];
        for (int i = 0; i < 64; i++) a += W2[t * 64 + i] * vvec[i];
        g_scale[b * 64 + t] = 1.f / (1.f + expf(-a));
    }
}

// ---------------------------------------------------------------------------
// Kernel 4: out = scale[b,c] * x. 8 float4/thread batched (MLP=8); streaming
// stores keep x L2-resident for the reads. (Best measured scale: 7.9us, R5.)
// ---------------------------------------------------------------------------
__global__ __launch_bounds__(256) void scale_kernel(const float4* __restrict__ x4,
                                                    float4* __restrict__ out4) {
    int base = blockIdx.x * 2048 + threadIdx.x;
    float4 v[8];
    float  s[8];
#pragma unroll
    for (int j = 0; j < 8; j++) {
        int i = base + j * 256;
        v[j] = __ldg(&x4[i]);
        s[j] = g_scale[i >> 10];   // 1024 float4 per (b,c)
    }
#pragma unroll
    for (int j = 0; j < 8; j++) {
        int i = base + j * 256;
        float4 o = v[j];
        o.x *= s[j]; o.y *= s[j]; o.z *= s[j]; o.w *= s[j];
        __stcs(&out4[i], o);
    }
}

extern "C" void kernel_launch(void* const* d_in, const int* in_sizes, int n_in,
                              void* d_out, int out_size) {
    const float* x  = (const float*)d_in[0];
    const float* w1 = (const float*)d_in[1];
    const float* b1 = (const float*)d_in[2];
    const float* w2 = (const float*)d_in[3];
    const float* b2 = (const float*)d_in[4];
    float* out = (float*)d_out;

    (void)in_sizes; (void)n_in; (void)out_size;

    const int ns_smem = 4 * 64 * LDP * (int)sizeof(float);
    cudaFuncSetAttribute(ns_kernel, cudaFuncAttributeMaxDynamicSharedMemorySize, ns_smem);

    dim3 gcov(NSPLIT, BATCH);
    cov_kernel<<<gcov, 256>>>(x);
    reduce_kernel<<<BATCH * CC * CC / 256, 256>>>();
    ns_kernel<<<BATCH, 256, ns_smem>>>(w1, b1, w2, b2);
    scale_kernel<<<(BATCH * CC * MM / 4) / 2048, 256>>>((const float4*)x, (float4*)out);
}